// round 3
// baseline (speedup 1.0000x reference)
#include <cuda_runtime.h>
#include <math.h>
#include <stdint.h>

#define NT 16384
#define HID 1024
#define NH 512
#define G3 1536
#define SCAN_CTAS 16

// ---------------- scratch (device globals; no allocation) ----------------
__device__ __align__(16) float d_xn[16384 * 1024];   // layernormed x
__device__ __align__(16) float d_ig[16384 * 1536];   // igates
__device__ __align__(16) float d_hs[16384 * 512];    // h trajectory
__device__ __align__(16) float d_g[16384 * 512];     // gelu(hs)
__device__ __align__(16) float d_y1[16384 * 1024];
__device__ __align__(16) float d_y2[16384 * 1024];

// ---------------- small helpers ----------------
__device__ __forceinline__ void ffma2(unsigned long long& d, unsigned long long a, unsigned long long b) {
    asm volatile("fma.rn.f32x2 %0, %1, %2, %0;" : "+l"(d) : "l"(a), "l"(b));
}
__device__ __forceinline__ unsigned long long pk2(float lo, float hi) {
    unsigned long long r;
    asm("mov.b64 %0, {%1, %2};" : "=l"(r) : "f"(lo), "f"(hi));
    return r;
}
__device__ __forceinline__ float2 up2(unsigned long long v) {
    float lo, hi;
    asm("mov.b64 {%0, %1}, %2;" : "=f"(lo), "=f"(hi) : "l"(v));
    return make_float2(lo, hi);
}
__device__ __forceinline__ float sigmoid_acc(float x) { return 1.0f / (1.0f + expf(-x)); }

__device__ __forceinline__ uint32_t smem_u32(const void* p) {
    uint32_t a;
    asm("{ .reg .u64 t; cvta.to.shared.u64 t, %1; cvt.u32.u64 %0, t; }" : "=r"(a) : "l"(p));
    return a;
}
__device__ __forceinline__ uint32_t mapa_u32(uint32_t laddr, uint32_t rank) {
    uint32_t r;
    asm("mapa.shared::cluster.u32 %0, %1, %2;" : "=r"(r) : "r"(laddr), "r"(rank));
    return r;
}
__device__ __forceinline__ void st_remote_f32(uint32_t addr, float v) {
    asm volatile("st.shared::cluster.f32 [%0], %1;" :: "r"(addr), "f"(v) : "memory");
}
__device__ __forceinline__ void mbar_init(uint32_t addr, uint32_t count) {
    asm volatile("mbarrier.init.shared.b64 [%0], %1;" :: "r"(addr), "r"(count) : "memory");
}
__device__ __forceinline__ void mbar_arrive_remote(uint32_t addr) {
    asm volatile("mbarrier.arrive.release.cluster.shared::cluster.b64 _, [%0];" :: "r"(addr) : "memory");
}
__device__ __forceinline__ void fence_cluster() {
    asm volatile("fence.acq_rel.cluster;" ::: "memory");
}
__device__ __forceinline__ void cluster_sync() {
    asm volatile("barrier.cluster.arrive.aligned;" ::: "memory");
    asm volatile("barrier.cluster.wait.aligned;" ::: "memory");
}
__device__ __forceinline__ void mbar_wait_parity(uint32_t addr, uint32_t parity) {
    uint32_t done;
    asm volatile(
        "{\n\t.reg .pred p;\n\t"
        "mbarrier.try_wait.parity.acquire.cluster.shared::cta.b64 p, [%1], %2;\n\t"
        "selp.b32 %0, 1, 0, p;\n\t}"
        : "=r"(done) : "r"(addr), "r"(parity) : "memory");
    if (!done) {
        asm volatile(
            "{\n\t.reg .pred P1;\n\t"
            "WL_%=:\n\t"
            "mbarrier.try_wait.parity.acquire.cluster.shared::cta.b64 P1, [%0], %1, 0x989680;\n\t"
            "@P1 bra.uni WD_%=;\n\t"
            "bra.uni WL_%=;\n\t"
            "WD_%=:\n\t}"
            :: "r"(addr), "r"(parity) : "memory");
    }
}

// ---------------- LayerNorm ----------------
__global__ __launch_bounds__(256) void ln_kernel(const float* __restrict__ x,
                                                 const float* __restrict__ w,
                                                 const float* __restrict__ bb,
                                                 float* __restrict__ xn) {
    const int row = blockIdx.x;
    const int tid = threadIdx.x;
    const float4 v = ((const float4*)(x + (size_t)row * HID))[tid];
    float s = v.x + v.y + v.z + v.w;
    float q = v.x * v.x + v.y * v.y + v.z * v.z + v.w * v.w;
#pragma unroll
    for (int off = 16; off; off >>= 1) {
        s += __shfl_xor_sync(0xffffffffu, s, off);
        q += __shfl_xor_sync(0xffffffffu, q, off);
    }
    __shared__ float rs[8], rq[8];
    __shared__ float mu_s, rstd_s;
    const int wid = tid >> 5, lane = tid & 31;
    if (lane == 0) { rs[wid] = s; rq[wid] = q; }
    __syncthreads();
    if (tid == 0) {
        float S = 0.f, Q = 0.f;
#pragma unroll
        for (int i = 0; i < 8; i++) { S += rs[i]; Q += rq[i]; }
        float mu = S * (1.0f / HID);
        float var = Q * (1.0f / HID) - mu * mu;
        mu_s = mu;
        rstd_s = rsqrtf(var + 1e-5f);
    }
    __syncthreads();
    const float mu = mu_s, rstd = rstd_s;
    const float4 wv = ((const float4*)w)[tid];
    const float4 bv = ((const float4*)bb)[tid];
    float4 o;
    o.x = (v.x - mu) * rstd * wv.x + bv.x;
    o.y = (v.y - mu) * rstd * wv.y + bv.y;
    o.z = (v.z - mu) * rstd * wv.z + bv.z;
    o.w = (v.w - mu) * rstd * wv.w + bv.w;
    ((float4*)(xn + (size_t)row * HID))[tid] = o;
}

// ---------------- SGEMM: C[M,N] = A[M,K] * B[N,K]^T + bias[N] ----------------
#define BM 128
#define BN 128
#define BKK 16
__global__ __launch_bounds__(256) void sgemm_nt(const float* __restrict__ A,
                                                const float* __restrict__ B,
                                                const float* __restrict__ bias,
                                                float* __restrict__ C,
                                                int M, int N, int K) {
    __shared__ float As[BKK][BM];
    __shared__ float Bs[BKK][BN];
    const int tid = threadIdx.x;
    const int bm = blockIdx.y, bn = blockIdx.x;
    const float* Ab = A + (size_t)bm * BM * K;
    const float* Bb = B + (size_t)bn * BN * K;
    const int lrow = tid >> 2;         // 0..63
    const int lcol = (tid & 3) << 2;   // 0,4,8,12
    const int tx = tid & 15, ty = tid >> 4;
    float acc[8][8];
#pragma unroll
    for (int i = 0; i < 8; i++)
#pragma unroll
        for (int jj = 0; jj < 8; jj++) acc[i][jj] = 0.f;

    for (int k0 = 0; k0 < K; k0 += BKK) {
        const float4 a0 = *(const float4*)(Ab + (size_t)lrow * K + k0 + lcol);
        const float4 a1 = *(const float4*)(Ab + (size_t)(lrow + 64) * K + k0 + lcol);
        const float4 b0 = *(const float4*)(Bb + (size_t)lrow * K + k0 + lcol);
        const float4 b1 = *(const float4*)(Bb + (size_t)(lrow + 64) * K + k0 + lcol);
        __syncthreads();
        As[lcol + 0][lrow] = a0.x; As[lcol + 1][lrow] = a0.y;
        As[lcol + 2][lrow] = a0.z; As[lcol + 3][lrow] = a0.w;
        As[lcol + 0][lrow + 64] = a1.x; As[lcol + 1][lrow + 64] = a1.y;
        As[lcol + 2][lrow + 64] = a1.z; As[lcol + 3][lrow + 64] = a1.w;
        Bs[lcol + 0][lrow] = b0.x; Bs[lcol + 1][lrow] = b0.y;
        Bs[lcol + 2][lrow] = b0.z; Bs[lcol + 3][lrow] = b0.w;
        Bs[lcol + 0][lrow + 64] = b1.x; Bs[lcol + 1][lrow + 64] = b1.y;
        Bs[lcol + 2][lrow + 64] = b1.z; Bs[lcol + 3][lrow + 64] = b1.w;
        __syncthreads();
#pragma unroll
        for (int k = 0; k < BKK; ++k) {
            float ar[8], br[8];
            *(float4*)&ar[0] = *(const float4*)&As[k][ty * 8];
            *(float4*)&ar[4] = *(const float4*)&As[k][ty * 8 + 4];
            *(float4*)&br[0] = *(const float4*)&Bs[k][tx * 8];
            *(float4*)&br[4] = *(const float4*)&Bs[k][tx * 8 + 4];
#pragma unroll
            for (int i = 0; i < 8; i++)
#pragma unroll
                for (int jj = 0; jj < 8; jj++) acc[i][jj] += ar[i] * br[jj];
        }
    }
#pragma unroll
    for (int i = 0; i < 8; i++) {
        const size_t row = (size_t)bm * BM + ty * 8 + i;
        float* Cr = C + row * N + bn * BN + tx * 8;
        const float* bp = bias + bn * BN + tx * 8;
#pragma unroll
        for (int jj = 0; jj < 8; jj++) Cr[jj] = acc[i][jj] + bp[jj];
    }
}

// ---------------- persistent GRU scan: 16-CTA cluster, DSMEM broadcast ----------------
__global__ __launch_bounds__(256, 1) void gru_scan(const float* __restrict__ w_hh,
                                                   const float* __restrict__ b_n,
                                                   const float* __restrict__ igates,
                                                   float* __restrict__ hs,
                                                   float* h_final) {
    __shared__ __align__(16) float sh_h[2][NH];          // double-buffered broadcast h
    __shared__ __align__(8) unsigned long long sh_mbar[2];

    const int tid = threadIdx.x;
    const int gidx = tid >> 3, li = tid & 7;
    uint32_t rank;
    asm("mov.u32 %0, %%cluster_ctarank;" : "=r"(rank));
    const int j = (int)rank * 32 + gidx;

    // preload weight slice into registers: rows (j, 512+j, 1024+j), cols li*4 + m*32 + {0..3}
    unsigned long long wr[32], wz[32], wn[32];
    {
        const float* br_ = w_hh + (size_t)j * NH + li * 4;
        const float* bz_ = w_hh + (size_t)(NH + j) * NH + li * 4;
        const float* bn_ = w_hh + (size_t)(2 * NH + j) * NH + li * 4;
#pragma unroll
        for (int m = 0; m < 16; m++) {
            float4 v = *(const float4*)(br_ + m * 32);
            wr[2 * m] = pk2(v.x, v.y); wr[2 * m + 1] = pk2(v.z, v.w);
            v = *(const float4*)(bz_ + m * 32);
            wz[2 * m] = pk2(v.x, v.y); wz[2 * m + 1] = pk2(v.z, v.w);
            v = *(const float4*)(bn_ + m * 32);
            wn[2 * m] = pk2(v.x, v.y); wn[2 * m + 1] = pk2(v.z, v.w);
        }
    }
    const float bnj = b_n[j];

    // init: zero h buffer 0, init mbarriers (16 arrivals each = one per CTA)
    sh_h[0][tid] = 0.0f;
    sh_h[0][tid + 256] = 0.0f;
    const uint32_t mbar_base = smem_u32(&sh_mbar[0]);
    const uint32_t h_base = smem_u32(&sh_h[0][0]);
    if (tid == 0) {
        mbar_init(mbar_base, SCAN_CTAS);
        mbar_init(mbar_base + 8, SCAN_CTAS);
    }
    __syncthreads();
    cluster_sync();   // mbar init + zeroed h visible cluster-wide

    float igr = 0.f, igz = 0.f, ign = 0.f;
    if (li == 0) {
        igr = igates[j];
        igz = igates[NH + j];
        ign = igates[2 * NH + j];
    }

    uint32_t ph0 = 0, ph1 = 0;

    for (int t = 0; t < NT; ++t) {
        const int buf = t & 1;
        if (t) {  // wait for this step's h buffer to be full (16 CTA arrivals)
            if (buf) { mbar_wait_parity(mbar_base + 8, ph1); ph1 ^= 1; }
            else     { mbar_wait_parity(mbar_base,     ph0); ph0 ^= 1; }
        }

        unsigned long long ar = 0ULL, az = 0ULL, an = 0ULL;
        const ulonglong2* hv2 = (const ulonglong2*)sh_h[buf];
#pragma unroll
        for (int m = 0; m < 16; m++) {
            const ulonglong2 h2 = hv2[li + 8 * m];
            ffma2(ar, wr[2 * m], h2.x); ffma2(ar, wr[2 * m + 1], h2.y);
            ffma2(az, wz[2 * m], h2.x); ffma2(az, wz[2 * m + 1], h2.y);
            ffma2(an, wn[2 * m], h2.x); ffma2(an, wn[2 * m + 1], h2.y);
        }
        float2 f;
        f = up2(ar); float sr = f.x + f.y;
        f = up2(az); float sz = f.x + f.y;
        f = up2(an); float sn = f.x + f.y;
#pragma unroll
        for (int off = 4; off; off >>= 1) {
            sr += __shfl_xor_sync(0xffffffffu, sr, off);
            sz += __shfl_xor_sync(0xffffffffu, sz, off);
            sn += __shfl_xor_sync(0xffffffffu, sn, off);
        }
        // lane 0 of each gate-group computes h_new; all 8 lanes share the
        // broadcast fan-out (2 remote ranks per lane) to pipeline DSMEM stores.
        float hnew = 0.0f;
        if (li == 0) {
            const float r = sigmoid_acc(igr + sr);
            const float z = sigmoid_acc(igz + sz);
            const float n = tanhf(ign + r * (sn + bnj));
            const float hprev = sh_h[buf][j];
            hnew = n + z * (hprev - n);
        }
        hnew = __shfl_sync(0xffffffffu, hnew, (tid & 31) & ~7);  // broadcast within gate-group
        if (t < NT - 1) {
            const uint32_t laddr = h_base + (uint32_t)((buf ^ 1) * NH + j) * 4u;
            st_remote_f32(mapa_u32(laddr, (uint32_t)li), hnew);
            st_remote_f32(mapa_u32(laddr, (uint32_t)li + 8u), hnew);
        }
        if (li == 0) {
            hs[(size_t)t * NH + j] = hnew;
            if (t == NT - 1) {
                if (h_final != nullptr) h_final[j] = hnew;
            } else {
                // prefetch next step's input gates
                const float* igp = igates + (size_t)(t + 1) * G3;
                igr = igp[j]; igz = igp[NH + j]; ign = igp[2 * NH + j];
            }
        }
        __syncthreads();                 // all writes of this CTA issued
        if (t < NT - 1 && tid == 0) {
            fence_cluster();             // publish remote stores
            const uint32_t marr = mbar_base + (uint32_t)(buf ^ 1) * 8u;
#pragma unroll
            for (uint32_t rr = 0; rr < SCAN_CTAS; rr++)
                mbar_arrive_remote(mapa_u32(marr, rr));
        }
    }
    cluster_sync();  // no CTA exits while peers' remote ops may target it
}

// ---------------- gelu (tanh approx, matches jax default) ----------------
__global__ __launch_bounds__(256) void gelu_kernel(const float* __restrict__ in,
                                                   float* __restrict__ outp) {
    const size_t i = (size_t)blockIdx.x * 256 + threadIdx.x;
    const float4 v = ((const float4*)in)[i];
    const float c0 = 0.7978845608028654f, c1 = 0.044715f;
    float4 o;
    o.x = 0.5f * v.x * (1.0f + tanhf(c0 * (v.x + c1 * v.x * v.x * v.x)));
    o.y = 0.5f * v.y * (1.0f + tanhf(c0 * (v.y + c1 * v.y * v.y * v.y)));
    o.z = 0.5f * v.z * (1.0f + tanhf(c0 * (v.z + c1 * v.z * v.z * v.z)));
    o.w = 0.5f * v.w * (1.0f + tanhf(c0 * (v.w + c1 * v.w * v.w * v.w)));
    ((float4*)outp)[i] = o;
}

// ---------------- final combine: out = x + y1 * sigmoid(y2) ----------------
__global__ __launch_bounds__(256) void combine_kernel(const float* __restrict__ x,
                                                      const float* __restrict__ y1,
                                                      const float* __restrict__ y2,
                                                      float* __restrict__ outp) {
    const size_t i = (size_t)blockIdx.x * 256 + threadIdx.x;
    const float4 xv = ((const float4*)x)[i];
    const float4 a = ((const float4*)y1)[i];
    const float4 s = ((const float4*)y2)[i];
    float4 o;
    o.x = xv.x + a.x * sigmoid_acc(s.x);
    o.y = xv.y + a.y * sigmoid_acc(s.y);
    o.z = xv.z + a.z * sigmoid_acc(s.z);
    o.w = xv.w + a.w * sigmoid_acc(s.w);
    ((float4*)outp)[i] = o;
}

// ---------------- launch ----------------
extern "C" void kernel_launch(void* const* d_in, const int* in_sizes, int n_in,
                              void* d_out, int out_size) {
    const float* x     = (const float*)d_in[0];
    const float* w_ih  = (const float*)d_in[1];
    const float* w_hh  = (const float*)d_in[2];
    const float* b     = (const float*)d_in[3];
    const float* b_n   = (const float*)d_in[4];
    const float* out_w  = (const float*)d_in[5];
    const float* out_b  = (const float*)d_in[6];
    const float* out2_w = (const float*)d_in[7];
    const float* out2_b = (const float*)d_in[8];
    const float* ln_w  = (const float*)d_in[9];
    const float* ln_b  = (const float*)d_in[10];

    float* outp = (float*)d_out;
    float* hfin = nullptr;
    float* ybase = outp;
    if (out_size == 512 + 16384 * 1024) {  // tuple (h_final, y) flattened
        hfin = outp;
        ybase = outp + 512;
    }

    void *p_xn, *p_ig, *p_hs, *p_g, *p_y1, *p_y2;
    cudaGetSymbolAddress(&p_xn, d_xn);
    cudaGetSymbolAddress(&p_ig, d_ig);
    cudaGetSymbolAddress(&p_hs, d_hs);
    cudaGetSymbolAddress(&p_g, d_g);
    cudaGetSymbolAddress(&p_y1, d_y1);
    cudaGetSymbolAddress(&p_y2, d_y2);

    ln_kernel<<<NT, 256>>>(x, ln_w, ln_b, (float*)p_xn);
    sgemm_nt<<<dim3(G3 / BN, NT / BM), 256>>>((const float*)p_xn, w_ih, b,
                                              (float*)p_ig, NT, G3, HID);

    // GRU scan: one 16-CTA cluster (nonportable size)
    cudaFuncSetAttribute(gru_scan, cudaFuncAttributeNonPortableClusterSizeAllowed, 1);
    {
        cudaLaunchConfig_t cfg = {};
        cfg.gridDim = dim3(SCAN_CTAS, 1, 1);
        cfg.blockDim = dim3(256, 1, 1);
        cfg.dynamicSmemBytes = 0;
        cfg.stream = 0;
        cudaLaunchAttribute attrs[1];
        attrs[0].id = cudaLaunchAttributeClusterDimension;
        attrs[0].val.clusterDim.x = SCAN_CTAS;
        attrs[0].val.clusterDim.y = 1;
        attrs[0].val.clusterDim.z = 1;
        cfg.attrs = attrs;
        cfg.numAttrs = 1;
        cudaLaunchKernelEx(&cfg, gru_scan, w_hh, b_n, (const float*)p_ig,
                           (float*)p_hs, hfin);
    }

    gelu_kernel<<<(NT * NH) / (4 * 256), 256>>>((const float*)p_hs, (float*)p_g);
    sgemm_nt<<<dim3(HID / BN, NT / BM), 256>>>((const float*)p_g, out_w, out_b,
                                               (float*)p_y1, NT, HID, NH);
    sgemm_nt<<<dim3(HID / BN, NT / BM), 256>>>((const float*)p_g, out2_w, out2_b,
                                               (float*)p_y2, NT, HID, NH);
    combine_kernel<<<(NT * HID) / (4 * 256), 256>>>(x, (const float*)p_y1,
                                                    (const float*)p_y2, ybase);
}

// round 8
// speedup vs baseline: 1.9888x; 1.9888x over previous
#include <cuda_runtime.h>
#include <math.h>
#include <stdint.h>

#define NT 16384
#define HID 1024
#define NH 512
#define G3 1536
#define SCAN_CTAS 16

// ---------------- scratch (device globals; no allocation) ----------------
__device__ __align__(16) float d_xn[16384 * 1024];   // layernormed x
__device__ __align__(16) float d_ig[16384 * 1536];   // igates
__device__ __align__(16) float d_hs[16384 * 512];    // h trajectory
__device__ __align__(16) float d_g[16384 * 512];     // gelu(hs)
__device__ __align__(16) float d_y1[16384 * 1024];
__device__ __align__(16) float d_y2[16384 * 1024];

// tagged h exchange: g_hx8[buf][j] = (f32 h[j] in low 32b, u32 tag in high 32b)
// published with st.release.gpu / polled with ld.acquire.gpu => morally strong,
// single-copy atomic, acquire orders consumers' subsequent loads.
__device__ __align__(16) unsigned long long g_hx8[2][NH];

// ---------------- small helpers ----------------
__device__ __forceinline__ void ffma2(unsigned long long& d, unsigned long long a, unsigned long long b) {
    asm volatile("fma.rn.f32x2 %0, %1, %2, %0;" : "+l"(d) : "l"(a), "l"(b));
}
__device__ __forceinline__ unsigned long long pk2(float lo, float hi) {
    unsigned long long r;
    asm("mov.b64 %0, {%1, %2};" : "=l"(r) : "f"(lo), "f"(hi));
    return r;
}
__device__ __forceinline__ float2 up2(unsigned long long v) {
    float lo, hi;
    asm("mov.b64 {%0, %1}, %2;" : "=f"(lo), "=f"(hi) : "l"(v));
    return make_float2(lo, hi);
}
__device__ __forceinline__ unsigned long long pkht(float h, unsigned tag) {
    unsigned long long r;
    asm("mov.b64 %0, {%1, %2};" : "=l"(r) : "f"(h), "r"(tag));
    return r;
}
__device__ __forceinline__ unsigned hx_tag(unsigned long long v) { return (unsigned)(v >> 32); }
__device__ __forceinline__ float hx_val(unsigned long long v) {
    float h; unsigned t;
    asm("mov.b64 {%0, %1}, %2;" : "=f"(h), "=r"(t) : "l"(v));
    (void)t;
    return h;
}
__device__ __forceinline__ float sigmoid_acc(float x) { return 1.0f / (1.0f + expf(-x)); }

// morally strong publish / poll (gpu scope)
__device__ __forceinline__ void st_rel_u64(unsigned long long* p, unsigned long long v) {
    asm volatile("st.release.gpu.global.u64 [%0], %1;" :: "l"(p), "l"(v) : "memory");
}
__device__ __forceinline__ unsigned long long ld_acq_u64(const unsigned long long* p) {
    unsigned long long v;
    asm volatile("ld.acquire.gpu.global.u64 %0, [%1];" : "=l"(v) : "l"(p) : "memory");
    return v;
}

// ---------------- LayerNorm ----------------
__global__ __launch_bounds__(256) void ln_kernel(const float* __restrict__ x,
                                                 const float* __restrict__ w,
                                                 const float* __restrict__ bb,
                                                 float* __restrict__ xn) {
    const int row = blockIdx.x;
    const int tid = threadIdx.x;
    const float4 v = ((const float4*)(x + (size_t)row * HID))[tid];
    float s = v.x + v.y + v.z + v.w;
    float q = v.x * v.x + v.y * v.y + v.z * v.z + v.w * v.w;
#pragma unroll
    for (int off = 16; off; off >>= 1) {
        s += __shfl_xor_sync(0xffffffffu, s, off);
        q += __shfl_xor_sync(0xffffffffu, q, off);
    }
    __shared__ float rs[8], rq[8];
    __shared__ float mu_s, rstd_s;
    const int wid = tid >> 5, lane = tid & 31;
    if (lane == 0) { rs[wid] = s; rq[wid] = q; }
    __syncthreads();
    if (tid == 0) {
        float S = 0.f, Q = 0.f;
#pragma unroll
        for (int i = 0; i < 8; i++) { S += rs[i]; Q += rq[i]; }
        float mu = S * (1.0f / HID);
        float var = Q * (1.0f / HID) - mu * mu;
        mu_s = mu;
        rstd_s = rsqrtf(var + 1e-5f);
    }
    __syncthreads();
    const float mu = mu_s, rstd = rstd_s;
    const float4 wv = ((const float4*)w)[tid];
    const float4 bv = ((const float4*)bb)[tid];
    float4 o;
    o.x = (v.x - mu) * rstd * wv.x + bv.x;
    o.y = (v.y - mu) * rstd * wv.y + bv.y;
    o.z = (v.z - mu) * rstd * wv.z + bv.z;
    o.w = (v.w - mu) * rstd * wv.w + bv.w;
    ((float4*)(xn + (size_t)row * HID))[tid] = o;
}

// ---------------- SGEMM: C[M,N] = A[M,K] * B[N,K]^T + bias[N] ----------------
#define BM 128
#define BN 128
#define BKK 16
__global__ __launch_bounds__(256) void sgemm_nt(const float* __restrict__ A,
                                                const float* __restrict__ B,
                                                const float* __restrict__ bias,
                                                float* __restrict__ C,
                                                int M, int N, int K) {
    __shared__ float As[BKK][BM];
    __shared__ float Bs[BKK][BN];
    const int tid = threadIdx.x;
    const int bm = blockIdx.y, bn = blockIdx.x;
    const float* Ab = A + (size_t)bm * BM * K;
    const float* Bb = B + (size_t)bn * BN * K;
    const int lrow = tid >> 2;         // 0..63
    const int lcol = (tid & 3) << 2;   // 0,4,8,12
    const int tx = tid & 15, ty = tid >> 4;
    float acc[8][8];
#pragma unroll
    for (int i = 0; i < 8; i++)
#pragma unroll
        for (int jj = 0; jj < 8; jj++) acc[i][jj] = 0.f;

    for (int k0 = 0; k0 < K; k0 += BKK) {
        const float4 a0 = *(const float4*)(Ab + (size_t)lrow * K + k0 + lcol);
        const float4 a1 = *(const float4*)(Ab + (size_t)(lrow + 64) * K + k0 + lcol);
        const float4 b0 = *(const float4*)(Bb + (size_t)lrow * K + k0 + lcol);
        const float4 b1 = *(const float4*)(Bb + (size_t)(lrow + 64) * K + k0 + lcol);
        __syncthreads();
        As[lcol + 0][lrow] = a0.x; As[lcol + 1][lrow] = a0.y;
        As[lcol + 2][lrow] = a0.z; As[lcol + 3][lrow] = a0.w;
        As[lcol + 0][lrow + 64] = a1.x; As[lcol + 1][lrow + 64] = a1.y;
        As[lcol + 2][lrow + 64] = a1.z; As[lcol + 3][lrow + 64] = a1.w;
        Bs[lcol + 0][lrow] = b0.x; Bs[lcol + 1][lrow] = b0.y;
        Bs[lcol + 2][lrow] = b0.z; Bs[lcol + 3][lrow] = b0.w;
        Bs[lcol + 0][lrow + 64] = b1.x; Bs[lcol + 1][lrow + 64] = b1.y;
        Bs[lcol + 2][lrow + 64] = b1.z; Bs[lcol + 3][lrow + 64] = b1.w;
        __syncthreads();
#pragma unroll
        for (int k = 0; k < BKK; ++k) {
            float ar[8], br[8];
            *(float4*)&ar[0] = *(const float4*)&As[k][ty * 8];
            *(float4*)&ar[4] = *(const float4*)&As[k][ty * 8 + 4];
            *(float4*)&br[0] = *(const float4*)&Bs[k][tx * 8];
            *(float4*)&br[4] = *(const float4*)&Bs[k][tx * 8 + 4];
#pragma unroll
            for (int i = 0; i < 8; i++)
#pragma unroll
                for (int jj = 0; jj < 8; jj++) acc[i][jj] += ar[i] * br[jj];
        }
    }
#pragma unroll
    for (int i = 0; i < 8; i++) {
        const size_t row = (size_t)bm * BM + ty * 8 + i;
        float* Cr = C + row * N + bn * BN + tx * 8;
        const float* bp = bias + bn * BN + tx * 8;
#pragma unroll
        for (int jj = 0; jj < 8; jj++) Cr[jj] = acc[i][jj] + bp[jj];
    }
}

// ---------------- scan init: seed tag buffers (runs before scan each launch) ----------------
__global__ void scan_init_kernel() {
    const int i = threadIdx.x;  // 512 threads
    st_rel_u64(&g_hx8[0][i], pkht(0.0f, 0u));           // h(0)=0, tag 0
    st_rel_u64(&g_hx8[1][i], pkht(0.0f, 0xFFFFFFFFu));  // sentinel
}

// ---------------- persistent GRU scan: 16 CTAs, release/acquire tagged L2 exchange ----------------
__global__ __launch_bounds__(256, 1) void gru_scan(const float* __restrict__ w_hh,
                                                   const float* __restrict__ b_n,
                                                   const float* __restrict__ igates,
                                                   float* __restrict__ hs,
                                                   float* h_final) {
    __shared__ __align__(16) float sh_h[2][NH];   // double-buffered staged h

    const int tid = threadIdx.x;
    const int gidx = tid >> 3, li = tid & 7;
    const int blk = blockIdx.x;
    const int j = blk * 32 + gidx;

    // preload weight slice into registers: rows (j, 512+j, 1024+j), cols li*4 + m*32 + {0..3}
    unsigned long long wr[32], wz[32], wn[32];
    {
        const float* br_ = w_hh + (size_t)j * NH + li * 4;
        const float* bz_ = w_hh + (size_t)(NH + j) * NH + li * 4;
        const float* bn_ = w_hh + (size_t)(2 * NH + j) * NH + li * 4;
#pragma unroll
        for (int m = 0; m < 16; m++) {
            float4 v = *(const float4*)(br_ + m * 32);
            wr[2 * m] = pk2(v.x, v.y); wr[2 * m + 1] = pk2(v.z, v.w);
            v = *(const float4*)(bz_ + m * 32);
            wz[2 * m] = pk2(v.x, v.y); wz[2 * m + 1] = pk2(v.z, v.w);
            v = *(const float4*)(bn_ + m * 32);
            wn[2 * m] = pk2(v.x, v.y); wn[2 * m + 1] = pk2(v.z, v.w);
        }
    }
    const float bnj = b_n[j];

    float igr = 0.f, igz = 0.f, ign = 0.f;
    if (li == 0) {
        igr = igates[j];
        igz = igates[NH + j];
        ign = igates[2 * NH + j];
    }

    for (int t = 0; t < NT; ++t) {
        const int buf = t & 1;
        // ---- consume: acquire-poll my two (h, tag) words until tags == t ----
        {
            const unsigned long long* gp = &g_hx8[buf][2 * tid];
            unsigned long long vx = ld_acq_u64(gp);
            while (hx_tag(vx) != (unsigned)t) vx = ld_acq_u64(gp);
            unsigned long long vy = ld_acq_u64(gp + 1);
            while (hx_tag(vy) != (unsigned)t) vy = ld_acq_u64(gp + 1);
            ((float2*)sh_h[buf])[tid] = make_float2(hx_val(vx), hx_val(vy));
        }
        __syncthreads();

        // ---- matvec on staged h ----
        unsigned long long ar = 0ULL, az = 0ULL, an = 0ULL;
        const ulonglong2* hv2 = (const ulonglong2*)sh_h[buf];
#pragma unroll
        for (int m = 0; m < 16; m++) {
            const ulonglong2 h2 = hv2[li + 8 * m];
            ffma2(ar, wr[2 * m], h2.x); ffma2(ar, wr[2 * m + 1], h2.y);
            ffma2(az, wz[2 * m], h2.x); ffma2(az, wz[2 * m + 1], h2.y);
            ffma2(an, wn[2 * m], h2.x); ffma2(an, wn[2 * m + 1], h2.y);
        }
        float2 f;
        f = up2(ar); float sr = f.x + f.y;
        f = up2(az); float sz = f.x + f.y;
        f = up2(an); float sn = f.x + f.y;
#pragma unroll
        for (int off = 4; off; off >>= 1) {
            sr += __shfl_xor_sync(0xffffffffu, sr, off);
            sz += __shfl_xor_sync(0xffffffffu, sz, off);
            sn += __shfl_xor_sync(0xffffffffu, sn, off);
        }

        if (li == 0) {
            const float r = sigmoid_acc(igr + sr);
            const float z = sigmoid_acc(igz + sz);
            const float n = tanhf(ign + r * (sn + bnj));
            const float hprev = sh_h[buf][j];
            const float hnew = n + z * (hprev - n);
            hs[(size_t)t * NH + j] = hnew;
            if (t == NT - 1) {
                if (h_final != nullptr) h_final[j] = hnew;
            } else {
                // publish (hnew, tag t+1) into the other buffer: release store
                st_rel_u64(&g_hx8[buf ^ 1][j], pkht(hnew, (unsigned)(t + 1)));
                const float* igp = igates + (size_t)(t + 1) * G3;
                igr = igp[j]; igz = igp[NH + j]; ign = igp[2 * NH + j];
            }
        }
    }
}

// ---------------- gelu (tanh approx, matches jax default) ----------------
__global__ __launch_bounds__(256) void gelu_kernel(const float* __restrict__ in,
                                                   float* __restrict__ outp) {
    const size_t i = (size_t)blockIdx.x * 256 + threadIdx.x;
    const float4 v = ((const float4*)in)[i];
    const float c0 = 0.7978845608028654f, c1 = 0.044715f;
    float4 o;
    o.x = 0.5f * v.x * (1.0f + tanhf(c0 * (v.x + c1 * v.x * v.x * v.x)));
    o.y = 0.5f * v.y * (1.0f + tanhf(c0 * (v.y + c1 * v.y * v.y * v.y)));
    o.z = 0.5f * v.z * (1.0f + tanhf(c0 * (v.z + c1 * v.z * v.z * v.z)));
    o.w = 0.5f * v.w * (1.0f + tanhf(c0 * (v.w + c1 * v.w * v.w * v.w)));
    ((float4*)outp)[i] = o;
}

// ---------------- final combine: out = x + y1 * sigmoid(y2) ----------------
__global__ __launch_bounds__(256) void combine_kernel(const float* __restrict__ x,
                                                      const float* __restrict__ y1,
                                                      const float* __restrict__ y2,
                                                      float* __restrict__ outp) {
    const size_t i = (size_t)blockIdx.x * 256 + threadIdx.x;
    const float4 xv = ((const float4*)x)[i];
    const float4 a = ((const float4*)y1)[i];
    const float4 s = ((const float4*)y2)[i];
    float4 o;
    o.x = xv.x + a.x * sigmoid_acc(s.x);
    o.y = xv.y + a.y * sigmoid_acc(s.y);
    o.z = xv.z + a.z * sigmoid_acc(s.z);
    o.w = xv.w + a.w * sigmoid_acc(s.w);
    ((float4*)outp)[i] = o;
}

// ---------------- launch ----------------
extern "C" void kernel_launch(void* const* d_in, const int* in_sizes, int n_in,
                              void* d_out, int out_size) {
    const float* x     = (const float*)d_in[0];
    const float* w_ih  = (const float*)d_in[1];
    const float* w_hh  = (const float*)d_in[2];
    const float* b     = (const float*)d_in[3];
    const float* b_n   = (const float*)d_in[4];
    const float* out_w  = (const float*)d_in[5];
    const float* out_b  = (const float*)d_in[6];
    const float* out2_w = (const float*)d_in[7];
    const float* out2_b = (const float*)d_in[8];
    const float* ln_w  = (const float*)d_in[9];
    const float* ln_b  = (const float*)d_in[10];

    float* outp = (float*)d_out;
    float* hfin = nullptr;
    float* ybase = outp;
    if (out_size == 512 + 16384 * 1024) {  // tuple (h_final, y) flattened
        hfin = outp;
        ybase = outp + 512;
    }

    void *p_xn, *p_ig, *p_hs, *p_g, *p_y1, *p_y2;
    cudaGetSymbolAddress(&p_xn, d_xn);
    cudaGetSymbolAddress(&p_ig, d_ig);
    cudaGetSymbolAddress(&p_hs, d_hs);
    cudaGetSymbolAddress(&p_g, d_g);
    cudaGetSymbolAddress(&p_y1, d_y1);
    cudaGetSymbolAddress(&p_y2, d_y2);

    scan_init_kernel<<<1, 512>>>();   // reseed tag buffers (replay-safe)
    ln_kernel<<<NT, 256>>>(x, ln_w, ln_b, (float*)p_xn);
    sgemm_nt<<<dim3(G3 / BN, NT / BM), 256>>>((const float*)p_xn, w_ih, b,
                                              (float*)p_ig, NT, G3, HID);
    gru_scan<<<SCAN_CTAS, 256>>>(w_hh, b_n, (const float*)p_ig, (float*)p_hs, hfin);
    gelu_kernel<<<(NT * NH) / (4 * 256), 256>>>((const float*)p_hs, (float*)p_g);
    sgemm_nt<<<dim3(HID / BN, NT / BM), 256>>>((const float*)p_g, out_w, out_b,
                                               (float*)p_y1, NT, HID, NH);
    sgemm_nt<<<dim3(HID / BN, NT / BM), 256>>>((const float*)p_g, out2_w, out2_b,
                                               (float*)p_y2, NT, HID, NH);
    combine_kernel<<<(NT * HID) / (4 * 256), 256>>>(x, (const float*)p_y1,
                                                    (const float*)p_y2, ybase);
}

// round 10
// speedup vs baseline: 3.1613x; 1.5896x over previous
#include <cuda_runtime.h>
#include <math.h>
#include <stdint.h>

#define NT 16384
#define HID 1024
#define NH 512
#define G3 1536
#define SCAN_CTAS 16

// ---------------- scratch (device globals; no allocation) ----------------
__device__ __align__(16) float d_xn[16384 * 1024];   // layernormed x
__device__ __align__(16) float d_ig[16384 * 1536];   // igates
__device__ __align__(16) float d_hs[16384 * 512];    // h trajectory
__device__ __align__(16) float d_g[16384 * 512];     // gelu(hs)
__device__ __align__(16) float d_y1[16384 * 1024];
__device__ __align__(16) float d_y2[16384 * 1024];

// tagged h exchange: g_hx8[buf][j] = (f32 h[j] low 32b, u32 tag high 32b).
// Published/polled with RELAXED gpu-scope ops: strong => single-copy atomic
// (payload travels inside the word, so no ordering needed), and relaxed
// polls pipeline (acquire polls serialize - that was R8's perf bug).
__device__ __align__(16) unsigned long long g_hx8[2][NH];

// ---------------- small helpers ----------------
__device__ __forceinline__ void ffma2(unsigned long long& d, unsigned long long a, unsigned long long b) {
    asm volatile("fma.rn.f32x2 %0, %1, %2, %0;" : "+l"(d) : "l"(a), "l"(b));
}
__device__ __forceinline__ unsigned long long pk2(float lo, float hi) {
    unsigned long long r;
    asm("mov.b64 %0, {%1, %2};" : "=l"(r) : "f"(lo), "f"(hi));
    return r;
}
__device__ __forceinline__ float2 up2(unsigned long long v) {
    float lo, hi;
    asm("mov.b64 {%0, %1}, %2;" : "=f"(lo), "=f"(hi) : "l"(v));
    return make_float2(lo, hi);
}
__device__ __forceinline__ unsigned long long pkht(float h, unsigned tag) {
    unsigned long long r;
    asm("mov.b64 %0, {%1, %2};" : "=l"(r) : "f"(h), "r"(tag));
    return r;
}
__device__ __forceinline__ unsigned hx_tag(unsigned long long v) { return (unsigned)(v >> 32); }
__device__ __forceinline__ float hx_val(unsigned long long v) {
    float h; unsigned t;
    asm("mov.b64 {%0, %1}, %2;" : "=f"(h), "=r"(t) : "l"(v));
    (void)t;
    return h;
}
__device__ __forceinline__ float sigmoid_acc(float x) { return 1.0f / (1.0f + expf(-x)); }
__device__ __forceinline__ float sigmoid_fast(float x) {
    return __fdividef(1.0f, 1.0f + __expf(-x));
}

// strong relaxed publish / poll (gpu scope): atomic, unordered, pipelineable
__device__ __forceinline__ void st_rlx_u64(unsigned long long* p, unsigned long long v) {
    asm volatile("st.relaxed.gpu.global.u64 [%0], %1;" :: "l"(p), "l"(v) : "memory");
}
__device__ __forceinline__ unsigned long long ld_rlx_u64(const unsigned long long* p) {
    unsigned long long v;
    asm volatile("ld.relaxed.gpu.global.u64 %0, [%1];" : "=l"(v) : "l"(p) : "memory");
    return v;
}

// ---------------- LayerNorm ----------------
__global__ __launch_bounds__(256) void ln_kernel(const float* __restrict__ x,
                                                 const float* __restrict__ w,
                                                 const float* __restrict__ bb,
                                                 float* __restrict__ xn) {
    const int row = blockIdx.x;
    const int tid = threadIdx.x;
    const float4 v = ((const float4*)(x + (size_t)row * HID))[tid];
    float s = v.x + v.y + v.z + v.w;
    float q = v.x * v.x + v.y * v.y + v.z * v.z + v.w * v.w;
#pragma unroll
    for (int off = 16; off; off >>= 1) {
        s += __shfl_xor_sync(0xffffffffu, s, off);
        q += __shfl_xor_sync(0xffffffffu, q, off);
    }
    __shared__ float rs[8], rq[8];
    __shared__ float mu_s, rstd_s;
    const int wid = tid >> 5, lane = tid & 31;
    if (lane == 0) { rs[wid] = s; rq[wid] = q; }
    __syncthreads();
    if (tid == 0) {
        float S = 0.f, Q = 0.f;
#pragma unroll
        for (int i = 0; i < 8; i++) { S += rs[i]; Q += rq[i]; }
        float mu = S * (1.0f / HID);
        float var = Q * (1.0f / HID) - mu * mu;
        mu_s = mu;
        rstd_s = rsqrtf(var + 1e-5f);
    }
    __syncthreads();
    const float mu = mu_s, rstd = rstd_s;
    const float4 wv = ((const float4*)w)[tid];
    const float4 bv = ((const float4*)bb)[tid];
    float4 o;
    o.x = (v.x - mu) * rstd * wv.x + bv.x;
    o.y = (v.y - mu) * rstd * wv.y + bv.y;
    o.z = (v.z - mu) * rstd * wv.z + bv.z;
    o.w = (v.w - mu) * rstd * wv.w + bv.w;
    ((float4*)(xn + (size_t)row * HID))[tid] = o;
}

// ---------------- SGEMM: C[M,N] = A[M,K] * B[N,K]^T + bias[N] ----------------
#define BM 128
#define BN 128
#define BKK 16
__global__ __launch_bounds__(256) void sgemm_nt(const float* __restrict__ A,
                                                const float* __restrict__ B,
                                                const float* __restrict__ bias,
                                                float* __restrict__ C,
                                                int M, int N, int K) {
    __shared__ float As[BKK][BM];
    __shared__ float Bs[BKK][BN];
    const int tid = threadIdx.x;
    const int bm = blockIdx.y, bn = blockIdx.x;
    const float* Ab = A + (size_t)bm * BM * K;
    const float* Bb = B + (size_t)bn * BN * K;
    const int lrow = tid >> 2;         // 0..63
    const int lcol = (tid & 3) << 2;   // 0,4,8,12
    const int tx = tid & 15, ty = tid >> 4;
    float acc[8][8];
#pragma unroll
    for (int i = 0; i < 8; i++)
#pragma unroll
        for (int jj = 0; jj < 8; jj++) acc[i][jj] = 0.f;

    for (int k0 = 0; k0 < K; k0 += BKK) {
        const float4 a0 = *(const float4*)(Ab + (size_t)lrow * K + k0 + lcol);
        const float4 a1 = *(const float4*)(Ab + (size_t)(lrow + 64) * K + k0 + lcol);
        const float4 b0 = *(const float4*)(Bb + (size_t)lrow * K + k0 + lcol);
        const float4 b1 = *(const float4*)(Bb + (size_t)(lrow + 64) * K + k0 + lcol);
        __syncthreads();
        As[lcol + 0][lrow] = a0.x; As[lcol + 1][lrow] = a0.y;
        As[lcol + 2][lrow] = a0.z; As[lcol + 3][lrow] = a0.w;
        As[lcol + 0][lrow + 64] = a1.x; As[lcol + 1][lrow + 64] = a1.y;
        As[lcol + 2][lrow + 64] = a1.z; As[lcol + 3][lrow + 64] = a1.w;
        Bs[lcol + 0][lrow] = b0.x; Bs[lcol + 1][lrow] = b0.y;
        Bs[lcol + 2][lrow] = b0.z; Bs[lcol + 3][lrow] = b0.w;
        Bs[lcol + 0][lrow + 64] = b1.x; Bs[lcol + 1][lrow + 64] = b1.y;
        Bs[lcol + 2][lrow + 64] = b1.z; Bs[lcol + 3][lrow + 64] = b1.w;
        __syncthreads();
#pragma unroll
        for (int k = 0; k < BKK; ++k) {
            float ar[8], br[8];
            *(float4*)&ar[0] = *(const float4*)&As[k][ty * 8];
            *(float4*)&ar[4] = *(const float4*)&As[k][ty * 8 + 4];
            *(float4*)&br[0] = *(const float4*)&Bs[k][tx * 8];
            *(float4*)&br[4] = *(const float4*)&Bs[k][tx * 8 + 4];
#pragma unroll
            for (int i = 0; i < 8; i++)
#pragma unroll
                for (int jj = 0; jj < 8; jj++) acc[i][jj] += ar[i] * br[jj];
        }
    }
#pragma unroll
    for (int i = 0; i < 8; i++) {
        const size_t row = (size_t)bm * BM + ty * 8 + i;
        float* Cr = C + row * N + bn * BN + tx * 8;
        const float* bp = bias + bn * BN + tx * 8;
#pragma unroll
        for (int jj = 0; jj < 8; jj++) Cr[jj] = acc[i][jj] + bp[jj];
    }
}

// ---------------- scan init: seed tag buffers (runs before scan each launch) ----------------
__global__ void scan_init_kernel() {
    const int i = threadIdx.x;  // 512 threads
    st_rlx_u64(&g_hx8[0][i], pkht(0.0f, 0u));           // h(0)=0, tag 0
    st_rlx_u64(&g_hx8[1][i], pkht(0.0f, 0xFFFFFFFFu));  // sentinel
}

// ---------------- persistent GRU scan: 16 CTAs, relaxed-atomic tagged L2 exchange ----------------
__global__ __launch_bounds__(256, 1) void gru_scan(const float* __restrict__ w_hh,
                                                   const float* __restrict__ b_n,
                                                   const float* __restrict__ igates,
                                                   float* __restrict__ hs,
                                                   float* h_final) {
    __shared__ __align__(16) float sh_h[2][NH];   // double-buffered staged h

    const int tid = threadIdx.x;
    const int gidx = tid >> 3, li = tid & 7;
    const int blk = blockIdx.x;
    const int j = blk * 32 + gidx;

    // preload weight slice into registers: rows (j, 512+j, 1024+j), cols li*4 + m*32 + {0..3}
    unsigned long long wr[32], wz[32], wn[32];
    {
        const float* br_ = w_hh + (size_t)j * NH + li * 4;
        const float* bz_ = w_hh + (size_t)(NH + j) * NH + li * 4;
        const float* bn_ = w_hh + (size_t)(2 * NH + j) * NH + li * 4;
#pragma unroll
        for (int m = 0; m < 16; m++) {
            float4 v = *(const float4*)(br_ + m * 32);
            wr[2 * m] = pk2(v.x, v.y); wr[2 * m + 1] = pk2(v.z, v.w);
            v = *(const float4*)(bz_ + m * 32);
            wz[2 * m] = pk2(v.x, v.y); wz[2 * m + 1] = pk2(v.z, v.w);
            v = *(const float4*)(bn_ + m * 32);
            wn[2 * m] = pk2(v.x, v.y); wn[2 * m + 1] = pk2(v.z, v.w);
        }
    }
    const float bnj = b_n[j];

    float igr = 0.f, igz = 0.f, ign = 0.f;
    if (li == 0) {
        igr = igates[j];
        igz = igates[NH + j];
        ign = igates[2 * NH + j];
    }

    for (int t = 0; t < NT; ++t) {
        const int buf = t & 1;
        // ---- consume: relaxed-poll my two (h, tag) words until both tags == t.
        // Relaxed loads are strong (atomic) but unordered => the two loads
        // overlap and iterations pipeline.
        {
            const unsigned long long* gp = &g_hx8[buf][2 * tid];
            unsigned long long vx = ld_rlx_u64(gp);
            unsigned long long vy = ld_rlx_u64(gp + 1);
            while (hx_tag(vx) != (unsigned)t || hx_tag(vy) != (unsigned)t) {
                vx = ld_rlx_u64(gp);
                vy = ld_rlx_u64(gp + 1);
            }
            ((float2*)sh_h[buf])[tid] = make_float2(hx_val(vx), hx_val(vy));
        }
        __syncthreads();

        // ---- matvec on staged h ----
        unsigned long long ar = 0ULL, az = 0ULL, an = 0ULL;
        const ulonglong2* hv2 = (const ulonglong2*)sh_h[buf];
#pragma unroll
        for (int m = 0; m < 16; m++) {
            const ulonglong2 h2 = hv2[li + 8 * m];
            ffma2(ar, wr[2 * m], h2.x); ffma2(ar, wr[2 * m + 1], h2.y);
            ffma2(az, wz[2 * m], h2.x); ffma2(az, wz[2 * m + 1], h2.y);
            ffma2(an, wn[2 * m], h2.x); ffma2(an, wn[2 * m + 1], h2.y);
        }
        float2 f;
        f = up2(ar); float sr = f.x + f.y;
        f = up2(az); float sz = f.x + f.y;
        f = up2(an); float sn = f.x + f.y;
#pragma unroll
        for (int off = 4; off; off >>= 1) {
            sr += __shfl_xor_sync(0xffffffffu, sr, off);
            sz += __shfl_xor_sync(0xffffffffu, sz, off);
            sn += __shfl_xor_sync(0xffffffffu, sn, off);
        }

        if (li == 0) {
            const float r = sigmoid_fast(igr + sr);
            const float z = sigmoid_fast(igz + sz);
            const float n = tanhf(ign + r * (sn + bnj));
            const float hprev = sh_h[buf][j];
            const float hnew = n + z * (hprev - n);
            if (t < NT - 1) {
                // publish FIRST (no ordering w.r.t. other stores => no stall)
                st_rlx_u64(&g_hx8[buf ^ 1][j], pkht(hnew, (unsigned)(t + 1)));
            }
            hs[(size_t)t * NH + j] = hnew;
            if (t == NT - 1) {
                if (h_final != nullptr) h_final[j] = hnew;
            } else {
                const float* igp = igates + (size_t)(t + 1) * G3;
                igr = igp[j]; igz = igp[NH + j]; ign = igp[2 * NH + j];
            }
        }
    }
}

// ---------------- gelu (tanh approx, matches jax default) ----------------
__global__ __launch_bounds__(256) void gelu_kernel(const float* __restrict__ in,
                                                   float* __restrict__ outp) {
    const size_t i = (size_t)blockIdx.x * 256 + threadIdx.x;
    const float4 v = ((const float4*)in)[i];
    const float c0 = 0.7978845608028654f, c1 = 0.044715f;
    float4 o;
    o.x = 0.5f * v.x * (1.0f + tanhf(c0 * (v.x + c1 * v.x * v.x * v.x)));
    o.y = 0.5f * v.y * (1.0f + tanhf(c0 * (v.y + c1 * v.y * v.y * v.y)));
    o.z = 0.5f * v.z * (1.0f + tanhf(c0 * (v.z + c1 * v.z * v.z * v.z)));
    o.w = 0.5f * v.w * (1.0f + tanhf(c0 * (v.w + c1 * v.w * v.w * v.w)));
    ((float4*)outp)[i] = o;
}

// ---------------- final combine: out = x + y1 * sigmoid(y2) ----------------
__global__ __launch_bounds__(256) void combine_kernel(const float* __restrict__ x,
                                                      const float* __restrict__ y1,
                                                      const float* __restrict__ y2,
                                                      float* __restrict__ outp) {
    const size_t i = (size_t)blockIdx.x * 256 + threadIdx.x;
    const float4 xv = ((const float4*)x)[i];
    const float4 a = ((const float4*)y1)[i];
    const float4 s = ((const float4*)y2)[i];
    float4 o;
    o.x = xv.x + a.x * sigmoid_acc(s.x);
    o.y = xv.y + a.y * sigmoid_acc(s.y);
    o.z = xv.z + a.z * sigmoid_acc(s.z);
    o.w = xv.w + a.w * sigmoid_acc(s.w);
    ((float4*)outp)[i] = o;
}

// ---------------- launch ----------------
extern "C" void kernel_launch(void* const* d_in, const int* in_sizes, int n_in,
                              void* d_out, int out_size) {
    const float* x     = (const float*)d_in[0];
    const float* w_ih  = (const float*)d_in[1];
    const float* w_hh  = (const float*)d_in[2];
    const float* b     = (const float*)d_in[3];
    const float* b_n   = (const float*)d_in[4];
    const float* out_w  = (const float*)d_in[5];
    const float* out_b  = (const float*)d_in[6];
    const float* out2_w = (const float*)d_in[7];
    const float* out2_b = (const float*)d_in[8];
    const float* ln_w  = (const float*)d_in[9];
    const float* ln_b  = (const float*)d_in[10];

    float* outp = (float*)d_out;
    float* hfin = nullptr;
    float* ybase = outp;
    if (out_size == 512 + 16384 * 1024) {  // tuple (h_final, y) flattened
        hfin = outp;
        ybase = outp + 512;
    }

    void *p_xn, *p_ig, *p_hs, *p_g, *p_y1, *p_y2;
    cudaGetSymbolAddress(&p_xn, d_xn);
    cudaGetSymbolAddress(&p_ig, d_ig);
    cudaGetSymbolAddress(&p_hs, d_hs);
    cudaGetSymbolAddress(&p_g, d_g);
    cudaGetSymbolAddress(&p_y1, d_y1);
    cudaGetSymbolAddress(&p_y2, d_y2);

    scan_init_kernel<<<1, 512>>>();   // reseed tag buffers (replay-safe)
    ln_kernel<<<NT, 256>>>(x, ln_w, ln_b, (float*)p_xn);
    sgemm_nt<<<dim3(G3 / BN, NT / BM), 256>>>((const float*)p_xn, w_ih, b,
                                              (float*)p_ig, NT, G3, HID);
    gru_scan<<<SCAN_CTAS, 256>>>(w_hh, b_n, (const float*)p_ig, (float*)p_hs, hfin);
    gelu_kernel<<<(NT * NH) / (4 * 256), 256>>>((const float*)p_hs, (float*)p_g);
    sgemm_nt<<<dim3(HID / BN, NT / BM), 256>>>((const float*)p_g, out_w, out_b,
                                               (float*)p_y1, NT, HID, NH);
    sgemm_nt<<<dim3(HID / BN, NT / BM), 256>>>((const float*)p_g, out2_w, out2_b,
                                               (float*)p_y2, NT, HID, NH);
    combine_kernel<<<(NT * HID) / (4 * 256), 256>>>(x, (const float*)p_y1,
                                                    (const float*)p_y2, ybase);
}